// round 1
// baseline (speedup 1.0000x reference)
#include <cuda_runtime.h>
#include <cstdint>

// Problem constants (fixed by the reference)
#define N_NODES 100000
#define E_EDGES 1000000
#define H_DIMC  124
#define CLS_DIMC 4
#define XDIM    128     // H_DIMC + CLS_DIMC
#define HIDDEN  256
#define CTOT    512     // A (256) || B (256)

// ---------------------------------------------------------------------------
// Static device scratch (no allocations allowed)
// ---------------------------------------------------------------------------
__device__ float g_X[(size_t)N_NODES * XDIM];        // [N,128]  = [h | softmax(cls)]
__device__ float g_C[(size_t)N_NODES * CTOT];        // [N,512]  = [A | B], A has +b1 folded
__device__ float g_Wg[(size_t)XDIM * CTOT];          // [128,512]: cols 0..255 = Wa, 256..511 = Wb
__device__ int   g_idx64;                            // 1 if src/dst are int64, 0 if int32

// ---------------------------------------------------------------------------
// Index width detection: int64 values are all < N_NODES; an int32 buffer
// reinterpreted as int64 gives values >= 2^32 (except ~1e-5 chance per elem),
// so checking 8 elements is deterministic in practice.
// ---------------------------------------------------------------------------
__global__ void detect_idx_kernel(const void* __restrict__ srcv) {
    const unsigned long long* p = (const unsigned long long*)srcv;
    int ok = 1;
    #pragma unroll
    for (int i = 0; i < 8; i++) {
        if (p[i] >= (unsigned long long)N_NODES) ok = 0;
    }
    g_idx64 = ok;
}

// ---------------------------------------------------------------------------
// Pack X = [h | softmax(cls)]  (one thread per element, grid covers N*128)
// ---------------------------------------------------------------------------
__global__ void prep_x_kernel(const float* __restrict__ h,
                              const float* __restrict__ cls) {
    int idx = blockIdx.x * blockDim.x + threadIdx.x;
    const int total = N_NODES * XDIM;
    if (idx >= total) return;
    int n = idx >> 7;
    int j = idx & 127;
    float v;
    if (j < H_DIMC) {
        v = h[(size_t)n * H_DIMC + j];
    } else {
        int c = j - H_DIMC;
        float4 l = *(const float4*)(cls + (size_t)n * CLS_DIMC);
        float m = fmaxf(fmaxf(l.x, l.y), fmaxf(l.z, l.w));
        float e0 = expf(l.x - m), e1 = expf(l.y - m);
        float e2 = expf(l.z - m), e3 = expf(l.w - m);
        float inv = 1.0f / (e0 + e1 + e2 + e3);
        float ec = (c == 0) ? e0 : (c == 1) ? e1 : (c == 2) ? e2 : e3;
        v = ec * inv;
    }
    g_X[idx] = v;
}

// ---------------------------------------------------------------------------
// Pack Wg[k][c]:  c<256 -> W1[k][c] (Wa);  c>=256 -> W1[130+k][c-256] (Wb)
// (W1 rows 128,129 are the polar rows, used directly in the edge kernel)
// ---------------------------------------------------------------------------
__global__ void prep_w_kernel(const float* __restrict__ W1) {
    int idx = blockIdx.x * blockDim.x + threadIdx.x;
    if (idx >= XDIM * CTOT) return;
    int k = idx >> 9;
    int c = idx & 511;
    float v = (c < HIDDEN) ? W1[(size_t)k * HIDDEN + c]
                           : W1[(size_t)(130 + k) * HIDDEN + (c - HIDDEN)];
    g_Wg[idx] = v;
}

// ---------------------------------------------------------------------------
// Node GEMM: C[N,512] = X[N,128] @ Wg[128,512], +b1 on the first 256 cols.
// Classic SGEMM: BM=128, BN=128, BK=16, 256 threads, 8x8 microtile.
// ---------------------------------------------------------------------------
#define BM 128
#define BN 128
#define BK 16
#define TM 8
#define TN 8

__global__ void __launch_bounds__(256) node_gemm_kernel(const float* __restrict__ b1) {
    __shared__ float As[BK][BM];
    __shared__ float Bs[BK][BN];

    const int m0 = blockIdx.y * BM;
    const int n0 = blockIdx.x * BN;
    const int tid = threadIdx.x;
    const int tr = tid >> 4;   // 0..15
    const int tc = tid & 15;   // 0..15

    float acc[TM][TN];
    #pragma unroll
    for (int i = 0; i < TM; i++)
        #pragma unroll
        for (int j = 0; j < TN; j++) acc[i][j] = 0.0f;

    for (int k0 = 0; k0 < XDIM; k0 += BK) {
        // Load A tile (BM x BK) from g_X, transpose into As[k][m]
        #pragma unroll
        for (int i = 0; i < 2; i++) {
            int f = tid + i * 256;           // 0..511 float4 slots
            int ar = f >> 2;                 // row within tile 0..127
            int ac = (f & 3) << 2;           // k offset 0,4,8,12
            int gm = m0 + ar;
            float4 v = make_float4(0.f, 0.f, 0.f, 0.f);
            if (gm < N_NODES)
                v = *(const float4*)(g_X + (size_t)gm * XDIM + k0 + ac);
            As[ac + 0][ar] = v.x;
            As[ac + 1][ar] = v.y;
            As[ac + 2][ar] = v.z;
            As[ac + 3][ar] = v.w;
        }
        // Load B tile (BK x BN) from g_Wg
        #pragma unroll
        for (int i = 0; i < 2; i++) {
            int f = tid + i * 256;
            int br = f >> 5;                 // 0..15
            int bc = (f & 31) << 2;          // 0..124
            *(float4*)(&Bs[br][bc]) =
                *(const float4*)(g_Wg + (size_t)(k0 + br) * CTOT + n0 + bc);
        }
        __syncthreads();

        #pragma unroll
        for (int k = 0; k < BK; k++) {
            float a[TM], b[TN];
            #pragma unroll
            for (int i = 0; i < TM; i += 4)
                *(float4*)(a + i) = *(const float4*)(&As[k][tr * TM + i]);
            #pragma unroll
            for (int j = 0; j < TN; j += 4)
                *(float4*)(b + j) = *(const float4*)(&Bs[k][tc * TN + j]);
            #pragma unroll
            for (int i = 0; i < TM; i++)
                #pragma unroll
                for (int j = 0; j < TN; j++)
                    acc[i][j] = fmaf(a[i], b[j], acc[i][j]);
        }
        __syncthreads();
    }

    // Epilogue: +b1 for cols < 256, store
    #pragma unroll
    for (int i = 0; i < TM; i++) {
        int m = m0 + tr * TM + i;
        if (m < N_NODES) {
            #pragma unroll
            for (int j = 0; j < TN; j += 4) {
                int n = n0 + tc * TN + j;
                float4 v;
                v.x = acc[i][j + 0];
                v.y = acc[i][j + 1];
                v.z = acc[i][j + 2];
                v.w = acc[i][j + 3];
                if (n < HIDDEN) {
                    v.x += b1[n + 0];
                    v.y += b1[n + 1];
                    v.z += b1[n + 2];
                    v.w += b1[n + 3];
                }
                *(float4*)(g_C + (size_t)m * CTOT + n) = v;
            }
        }
    }
}

// ---------------------------------------------------------------------------
// Edge kernel: one warp per edge (grid-stride).
// z = A[src] + B[dst] + p0*Wp0 + p1*Wp1  (b1 already folded into A)
// then LayerNorm -> ReLU -> dot with W2 columns, + b2.
// Each lane owns 8 consecutive hidden channels (lane*8 .. lane*8+7).
// Per-lane weights loaded once into registers (amortized over many edges).
// ---------------------------------------------------------------------------
__global__ void __launch_bounds__(256) edge_kernel(
    const float* __restrict__ polar,
    const void*  __restrict__ srcv,
    const void*  __restrict__ dstv,
    const float* __restrict__ W1,
    const float* __restrict__ gamma,
    const float* __restrict__ beta,
    const float* __restrict__ W2,
    const float* __restrict__ b2,
    float* __restrict__ out)
{
    const int lane = threadIdx.x & 31;
    const int warp = (blockIdx.x * blockDim.x + threadIdx.x) >> 5;
    const int nwarps = (gridDim.x * blockDim.x) >> 5;
    const int j0 = lane * 8;

    float wp0[8], wp1[8], ga[8], be[8], w2a[8], w2b[8];
    #pragma unroll
    for (int i = 0; i < 8; i++) {
        int j = j0 + i;
        wp0[i] = W1[(size_t)128 * HIDDEN + j];
        wp1[i] = W1[(size_t)129 * HIDDEN + j];
        ga[i]  = gamma[j];
        be[i]  = beta[j];
        w2a[i] = W2[j * 2 + 0];
        w2b[i] = W2[j * 2 + 1];
    }
    const float bias0 = b2[0], bias1 = b2[1];

    const bool is64 = (g_idx64 != 0);
    const long long* src64 = (const long long*)srcv;
    const long long* dst64 = (const long long*)dstv;
    const int*       src32 = (const int*)srcv;
    const int*       dst32 = (const int*)dstv;

    for (int e = warp; e < E_EDGES; e += nwarps) {
        int s = is64 ? (int)src64[e] : src32[e];
        int d = is64 ? (int)dst64[e] : dst32[e];
        float2 p = *(const float2*)(polar + (size_t)e * 2);

        const float4* pa = (const float4*)(g_C + (size_t)s * CTOT) + lane * 2;
        const float4* pb = (const float4*)(g_C + (size_t)d * CTOT + HIDDEN) + lane * 2;
        float4 a0 = pa[0], a1 = pa[1];
        float4 bb0 = pb[0], bb1 = pb[1];

        float z[8];
        z[0] = a0.x + bb0.x; z[1] = a0.y + bb0.y;
        z[2] = a0.z + bb0.z; z[3] = a0.w + bb0.w;
        z[4] = a1.x + bb1.x; z[5] = a1.y + bb1.y;
        z[6] = a1.z + bb1.z; z[7] = a1.w + bb1.w;
        #pragma unroll
        for (int i = 0; i < 8; i++)
            z[i] = fmaf(p.x, wp0[i], fmaf(p.y, wp1[i], z[i]));

        float s1 = 0.f, s2 = 0.f;
        #pragma unroll
        for (int i = 0; i < 8; i++) {
            s1 += z[i];
            s2 = fmaf(z[i], z[i], s2);
        }
        #pragma unroll
        for (int o = 16; o > 0; o >>= 1) {
            s1 += __shfl_xor_sync(0xFFFFFFFFu, s1, o);
            s2 += __shfl_xor_sync(0xFFFFFFFFu, s2, o);
        }
        const float mean = s1 * (1.0f / 256.0f);
        const float var  = fmaf(-mean, mean, s2 * (1.0f / 256.0f));
        const float rstd = rsqrtf(var + 1e-5f);

        float acc0 = 0.f, acc1 = 0.f;
        #pragma unroll
        for (int i = 0; i < 8; i++) {
            float y = fmaf((z[i] - mean) * rstd, ga[i], be[i]);
            y = fmaxf(y, 0.0f);
            acc0 = fmaf(y, w2a[i], acc0);
            acc1 = fmaf(y, w2b[i], acc1);
        }
        #pragma unroll
        for (int o = 16; o > 0; o >>= 1) {
            acc0 += __shfl_xor_sync(0xFFFFFFFFu, acc0, o);
            acc1 += __shfl_xor_sync(0xFFFFFFFFu, acc1, o);
        }
        if (lane == 0) {
            out[(size_t)e * 2 + 0] = acc0 + bias0;
            out[(size_t)e * 2 + 1] = acc1 + bias1;
        }
    }
}

// ---------------------------------------------------------------------------
// Launch
// ---------------------------------------------------------------------------
extern "C" void kernel_launch(void* const* d_in, const int* in_sizes, int n_in,
                              void* d_out, int out_size) {
    const float* h     = (const float*)d_in[0];
    const float* cls   = (const float*)d_in[1];
    const float* polar = (const float*)d_in[2];
    const void*  src   = d_in[3];
    const void*  dst   = d_in[4];
    const float* W1    = (const float*)d_in[5];
    const float* b1    = (const float*)d_in[6];
    const float* gamma = (const float*)d_in[7];
    const float* beta  = (const float*)d_in[8];
    const float* W2    = (const float*)d_in[9];
    const float* b2    = (const float*)d_in[10];
    float* out = (float*)d_out;

    (void)in_sizes; (void)n_in; (void)out_size;

    // 1) index dtype detection (int64 vs int32)
    detect_idx_kernel<<<1, 1>>>(src);

    // 2) pack X = [h | softmax(cls)]
    {
        int total = N_NODES * XDIM;
        int threads = 256;
        int blocks = (total + threads - 1) / threads;
        prep_x_kernel<<<blocks, threads>>>(h, cls);
    }

    // 3) pack Wg
    {
        int total = XDIM * CTOT;
        prep_w_kernel<<<(total + 255) / 256, 256>>>(W1);
    }

    // 4) node GEMM: C = X @ Wg (+b1 on first half)
    {
        dim3 grid(CTOT / BN, (N_NODES + BM - 1) / BM);  // (4, 782)
        node_gemm_kernel<<<grid, 256>>>(b1);
    }

    // 5) edge pass
    {
        edge_kernel<<<2048, 256>>>(polar, src, dst, W1, gamma, beta, W2, b2, out);
    }
}

// round 2
// speedup vs baseline: 1.2477x; 1.2477x over previous
#include <cuda_runtime.h>
#include <cuda_fp16.h>
#include <cstdint>

// Problem constants (fixed by the reference)
#define N_NODES 100000
#define E_EDGES 1000000
#define H_DIMC  124
#define CLS_DIMC 4
#define XDIM    128     // H_DIMC + CLS_DIMC
#define HIDDEN  256
#define CTOT    512     // A (256) || B (256)

// ---------------------------------------------------------------------------
// Static device scratch (no allocations allowed)
// ---------------------------------------------------------------------------
__device__ float  g_X[(size_t)N_NODES * XDIM];        // [N,128]  = [h | softmax(cls)]
__device__ __half g_Ch[(size_t)N_NODES * CTOT];       // [N,512] fp16 = [A | B], A has +b1 folded (102MB: fits L2)
__device__ float  g_Wg[(size_t)XDIM * CTOT];          // [128,512]: cols 0..255 = Wa, 256..511 = Wb
__device__ int    g_idx64;                            // 1 if src/dst are int64, 0 if int32

// ---------------------------------------------------------------------------
// Index width detection
// ---------------------------------------------------------------------------
__global__ void detect_idx_kernel(const void* __restrict__ srcv) {
    const unsigned long long* p = (const unsigned long long*)srcv;
    int ok = 1;
    #pragma unroll
    for (int i = 0; i < 8; i++) {
        if (p[i] >= (unsigned long long)N_NODES) ok = 0;
    }
    g_idx64 = ok;
}

// ---------------------------------------------------------------------------
// Pack X = [h | softmax(cls)]
// ---------------------------------------------------------------------------
__global__ void prep_x_kernel(const float* __restrict__ h,
                              const float* __restrict__ cls) {
    int idx = blockIdx.x * blockDim.x + threadIdx.x;
    const int total = N_NODES * XDIM;
    if (idx >= total) return;
    int n = idx >> 7;
    int j = idx & 127;
    float v;
    if (j < H_DIMC) {
        v = h[(size_t)n * H_DIMC + j];
    } else {
        int c = j - H_DIMC;
        float4 l = *(const float4*)(cls + (size_t)n * CLS_DIMC);
        float m = fmaxf(fmaxf(l.x, l.y), fmaxf(l.z, l.w));
        float e0 = expf(l.x - m), e1 = expf(l.y - m);
        float e2 = expf(l.z - m), e3 = expf(l.w - m);
        float inv = 1.0f / (e0 + e1 + e2 + e3);
        float ec = (c == 0) ? e0 : (c == 1) ? e1 : (c == 2) ? e2 : e3;
        v = ec * inv;
    }
    g_X[idx] = v;
}

// ---------------------------------------------------------------------------
// Pack Wg[k][c]:  c<256 -> W1[k][c] (Wa);  c>=256 -> W1[130+k][c-256] (Wb)
// ---------------------------------------------------------------------------
__global__ void prep_w_kernel(const float* __restrict__ W1) {
    int idx = blockIdx.x * blockDim.x + threadIdx.x;
    if (idx >= XDIM * CTOT) return;
    int k = idx >> 9;
    int c = idx & 511;
    float v = (c < HIDDEN) ? W1[(size_t)k * HIDDEN + c]
                           : W1[(size_t)(130 + k) * HIDDEN + (c - HIDDEN)];
    g_Wg[idx] = v;
}

// ---------------------------------------------------------------------------
// Node GEMM: C[N,512] = X[N,128] @ Wg[128,512], +b1 on the first 256 cols.
// BM=128, BN=128, BK=16, 256 threads, 8x8 microtile.
// Register-staged double buffering: prefetch next K-tile into regs during
// compute of the current one. Output stored fp16.
// ---------------------------------------------------------------------------
#define BM 128
#define BN 128
#define BK 16
#define TM 8
#define TN 8
#define NKB (XDIM / BK)   // 8

__global__ void __launch_bounds__(256) node_gemm_kernel(const float* __restrict__ b1) {
    __shared__ float As[BK][BM];
    __shared__ float Bs[BK][BN];

    const int m0 = blockIdx.y * BM;
    const int n0 = blockIdx.x * BN;
    const int tid = threadIdx.x;
    const int tr = tid >> 4;   // 0..15
    const int tc = tid & 15;   // 0..15

    // A staging slots: f0 = tid, f1 = tid + 256  (512 float4 slots total)
    const int a_r0 = tid >> 2;              // row within tile 0..63
    const int a_c0 = (tid & 3) << 2;        // k offset 0,4,8,12
    const int a_r1 = (tid + 256) >> 2;      // 64..127
    const int a_c1 = a_c0;                  // ((tid+256)&3)<<2 == a_c0
    // B staging slots
    const int b_r0 = tid >> 5;              // 0..7
    const int b_c0 = (tid & 31) << 2;
    const int b_r1 = b_r0 + 8;              // 8..15
    const int b_c1 = b_c0;

    const int gm0 = m0 + a_r0;
    const int gm1 = m0 + a_r1;
    const bool m0ok = (gm0 < N_NODES);
    const bool m1ok = (gm1 < N_NODES);

    float acc[TM][TN];
    #pragma unroll
    for (int i = 0; i < TM; i++)
        #pragma unroll
        for (int j = 0; j < TN; j++) acc[i][j] = 0.0f;

    float4 ra0, ra1, rb0, rb1;

    // prefetch tile 0
    ra0 = m0ok ? *(const float4*)(g_X + (size_t)gm0 * XDIM + a_c0) : make_float4(0,0,0,0);
    ra1 = m1ok ? *(const float4*)(g_X + (size_t)gm1 * XDIM + a_c1) : make_float4(0,0,0,0);
    rb0 = *(const float4*)(g_Wg + (size_t)b_r0 * CTOT + n0 + b_c0);
    rb1 = *(const float4*)(g_Wg + (size_t)b_r1 * CTOT + n0 + b_c1);

    for (int kb = 0; kb < NKB; kb++) {
        // store staged regs into smem (A transposed)
        As[a_c0 + 0][a_r0] = ra0.x;
        As[a_c0 + 1][a_r0] = ra0.y;
        As[a_c0 + 2][a_r0] = ra0.z;
        As[a_c0 + 3][a_r0] = ra0.w;
        As[a_c1 + 0][a_r1] = ra1.x;
        As[a_c1 + 1][a_r1] = ra1.y;
        As[a_c1 + 2][a_r1] = ra1.z;
        As[a_c1 + 3][a_r1] = ra1.w;
        *(float4*)(&Bs[b_r0][b_c0]) = rb0;
        *(float4*)(&Bs[b_r1][b_c1]) = rb1;
        __syncthreads();

        // prefetch next tile into regs (overlaps with compute below)
        if (kb + 1 < NKB) {
            int k0 = (kb + 1) * BK;
            ra0 = m0ok ? *(const float4*)(g_X + (size_t)gm0 * XDIM + k0 + a_c0) : make_float4(0,0,0,0);
            ra1 = m1ok ? *(const float4*)(g_X + (size_t)gm1 * XDIM + k0 + a_c1) : make_float4(0,0,0,0);
            rb0 = *(const float4*)(g_Wg + (size_t)(k0 + b_r0) * CTOT + n0 + b_c0);
            rb1 = *(const float4*)(g_Wg + (size_t)(k0 + b_r1) * CTOT + n0 + b_c1);
        }

        #pragma unroll
        for (int k = 0; k < BK; k++) {
            float a[TM], b[TN];
            #pragma unroll
            for (int i = 0; i < TM; i += 4)
                *(float4*)(a + i) = *(const float4*)(&As[k][tr * TM + i]);
            #pragma unroll
            for (int j = 0; j < TN; j += 4)
                *(float4*)(b + j) = *(const float4*)(&Bs[k][tc * TN + j]);
            #pragma unroll
            for (int i = 0; i < TM; i++)
                #pragma unroll
                for (int j = 0; j < TN; j++)
                    acc[i][j] = fmaf(a[i], b[j], acc[i][j]);
        }
        __syncthreads();
    }

    // Epilogue: +b1 for cols < 256, convert to fp16, store 8 halves (16B) per row
    const int n = n0 + tc * TN;
    float badd[TN];
    #pragma unroll
    for (int j = 0; j < TN; j++)
        badd[j] = (n + j < HIDDEN) ? b1[n + j] : 0.0f;

    #pragma unroll
    for (int i = 0; i < TM; i++) {
        int m = m0 + tr * TM + i;
        if (m < N_NODES) {
            __half hv[TN];
            #pragma unroll
            for (int j = 0; j < TN; j++)
                hv[j] = __float2half_rn(acc[i][j] + badd[j]);
            *(uint4*)(g_Ch + (size_t)m * CTOT + n) = *(const uint4*)hv;
        }
    }
}

// ---------------------------------------------------------------------------
// Edge kernel: one warp per edge (grid-stride), fp16 gathered rows.
// z = A[src] + B[dst] + p0*Wp0 + p1*Wp1  (b1 already folded into A)
// then LayerNorm -> ReLU -> dot with W2 columns, + b2.
// Each lane owns 8 consecutive hidden channels: one uint4 (8 halves) per row.
// ---------------------------------------------------------------------------
__global__ void __launch_bounds__(256) edge_kernel(
    const float* __restrict__ polar,
    const void*  __restrict__ srcv,
    const void*  __restrict__ dstv,
    const float* __restrict__ W1,
    const float* __restrict__ gamma,
    const float* __restrict__ beta,
    const float* __restrict__ W2,
    const float* __restrict__ b2,
    float* __restrict__ out)
{
    const int lane = threadIdx.x & 31;
    const int warp = (blockIdx.x * blockDim.x + threadIdx.x) >> 5;
    const int nwarps = (gridDim.x * blockDim.x) >> 5;
    const int j0 = lane * 8;

    float wp0[8], wp1[8], ga[8], be[8], w2a[8], w2b[8];
    #pragma unroll
    for (int i = 0; i < 8; i++) {
        int j = j0 + i;
        wp0[i] = W1[(size_t)128 * HIDDEN + j];
        wp1[i] = W1[(size_t)129 * HIDDEN + j];
        ga[i]  = gamma[j];
        be[i]  = beta[j];
        w2a[i] = W2[j * 2 + 0];
        w2b[i] = W2[j * 2 + 1];
    }
    const float bias0 = b2[0], bias1 = b2[1];

    const bool is64 = (g_idx64 != 0);
    const long long* src64 = (const long long*)srcv;
    const long long* dst64 = (const long long*)dstv;
    const int*       src32 = (const int*)srcv;
    const int*       dst32 = (const int*)dstv;

    for (int e = warp; e < E_EDGES; e += nwarps) {
        int s = is64 ? (int)src64[e] : src32[e];
        int d = is64 ? (int)dst64[e] : dst32[e];
        float2 p = *(const float2*)(polar + (size_t)e * 2);

        uint4 va = *(const uint4*)(g_Ch + (size_t)s * CTOT + j0);
        uint4 vb = *(const uint4*)(g_Ch + (size_t)d * CTOT + HIDDEN + j0);

        float2 a01 = __half22float2(*reinterpret_cast<const __half2*>(&va.x));
        float2 a23 = __half22float2(*reinterpret_cast<const __half2*>(&va.y));
        float2 a45 = __half22float2(*reinterpret_cast<const __half2*>(&va.z));
        float2 a67 = __half22float2(*reinterpret_cast<const __half2*>(&va.w));
        float2 b01 = __half22float2(*reinterpret_cast<const __half2*>(&vb.x));
        float2 b23 = __half22float2(*reinterpret_cast<const __half2*>(&vb.y));
        float2 b45 = __half22float2(*reinterpret_cast<const __half2*>(&vb.z));
        float2 b67 = __half22float2(*reinterpret_cast<const __half2*>(&vb.w));

        float z[8];
        z[0] = a01.x + b01.x; z[1] = a01.y + b01.y;
        z[2] = a23.x + b23.x; z[3] = a23.y + b23.y;
        z[4] = a45.x + b45.x; z[5] = a45.y + b45.y;
        z[6] = a67.x + b67.x; z[7] = a67.y + b67.y;
        #pragma unroll
        for (int i = 0; i < 8; i++)
            z[i] = fmaf(p.x, wp0[i], fmaf(p.y, wp1[i], z[i]));

        float s1 = 0.f, s2 = 0.f;
        #pragma unroll
        for (int i = 0; i < 8; i++) {
            s1 += z[i];
            s2 = fmaf(z[i], z[i], s2);
        }
        #pragma unroll
        for (int o = 16; o > 0; o >>= 1) {
            s1 += __shfl_xor_sync(0xFFFFFFFFu, s1, o);
            s2 += __shfl_xor_sync(0xFFFFFFFFu, s2, o);
        }
        const float mean = s1 * (1.0f / 256.0f);
        const float var  = fmaf(-mean, mean, s2 * (1.0f / 256.0f));
        const float rstd = rsqrtf(var + 1e-5f);

        float acc0 = 0.f, acc1 = 0.f;
        #pragma unroll
        for (int i = 0; i < 8; i++) {
            float y = fmaf((z[i] - mean) * rstd, ga[i], be[i]);
            y = fmaxf(y, 0.0f);
            acc0 = fmaf(y, w2a[i], acc0);
            acc1 = fmaf(y, w2b[i], acc1);
        }
        #pragma unroll
        for (int o = 16; o > 0; o >>= 1) {
            acc0 += __shfl_xor_sync(0xFFFFFFFFu, acc0, o);
            acc1 += __shfl_xor_sync(0xFFFFFFFFu, acc1, o);
        }
        if (lane == 0) {
            out[(size_t)e * 2 + 0] = acc0 + bias0;
            out[(size_t)e * 2 + 1] = acc1 + bias1;
        }
    }
}

// ---------------------------------------------------------------------------
// Launch
// ---------------------------------------------------------------------------
extern "C" void kernel_launch(void* const* d_in, const int* in_sizes, int n_in,
                              void* d_out, int out_size) {
    const float* h     = (const float*)d_in[0];
    const float* cls   = (const float*)d_in[1];
    const float* polar = (const float*)d_in[2];
    const void*  src   = d_in[3];
    const void*  dst   = d_in[4];
    const float* W1    = (const float*)d_in[5];
    const float* b1    = (const float*)d_in[6];
    const float* gamma = (const float*)d_in[7];
    const float* beta  = (const float*)d_in[8];
    const float* W2    = (const float*)d_in[9];
    const float* b2    = (const float*)d_in[10];
    float* out = (float*)d_out;

    (void)in_sizes; (void)n_in; (void)out_size;

    detect_idx_kernel<<<1, 1>>>(src);

    {
        int total = N_NODES * XDIM;
        prep_x_kernel<<<(total + 255) / 256, 256>>>(h, cls);
    }
    {
        int total = XDIM * CTOT;
        prep_w_kernel<<<(total + 255) / 256, 256>>>(W1);
    }
    {
        dim3 grid(CTOT / BN, (N_NODES + BM - 1) / BM);  // (4, 782)
        node_gemm_kernel<<<grid, 256>>>(b1);
    }
    {
        edge_kernel<<<2048, 256>>>(polar, src, dst, W1, gamma, beta, W2, b2, out);
    }
}